// round 5
// baseline (speedup 1.0000x reference)
#include <cuda_runtime.h>
#include <cstdint>

// Problem constants (fixed by the reference)
#define NUM_VERTS 6890
#define NUM_FACES 13776
#define HH 1024
#define WW 1024
#define NB 16
#define HW (HH * WW)

// Each thread handles 4 consecutive pixels -> 12 output floats per batch
// (3 aligned float4 stores), written to all 16 batch slices.
// faces/pix are int32 (harness canonicalizes int64 inputs to int32).
__global__ __launch_bounds__(256) void uvrender_kernel(
    const float* __restrict__ verts,   // (16, 6890, 3) fp32; only batch 0 used
    const int*   __restrict__ faces,   // (13776, 3) int32
    const int*   __restrict__ pix,     // (1024, 1024) int32
    const float* __restrict__ bary,    // (1024, 1024, 3) fp32
    float* __restrict__ out)           // (16, 1024, 1024, 3) fp32
{
    const int t = blockIdx.x * blockDim.x + threadIdx.x;
    const int p0 = t * 4;
    if (p0 >= HW) return;

    // 4 pix_to_face values: one 16B load
    const int4 pv = *reinterpret_cast<const int4*>(pix + p0);
    int pf[4] = {pv.x, pv.y, pv.z, pv.w};

    // 12 bary floats (48B, 16B-aligned)
    const float4 b0 = *reinterpret_cast<const float4*>(bary + (size_t)p0 * 3);
    const float4 b1 = *reinterpret_cast<const float4*>(bary + (size_t)p0 * 3 + 4);
    const float4 b2 = *reinterpret_cast<const float4*>(bary + (size_t)p0 * 3 + 8);
    float bc[12] = {b0.x, b0.y, b0.z, b0.w,
                    b1.x, b1.y, b1.z, b1.w,
                    b2.x, b2.y, b2.z, b2.w};

    float r[12];
#pragma unroll
    for (int i = 0; i < 4; i++) {
        float ox = 0.f, oy = 0.f, oz = 0.f;
        int f = pf[i];
        if (f >= 0) {
            // defensive clamp (dead code if dtype theory is right)
            f = min(f, NUM_FACES - 1);
            int v0 = __ldg(faces + f * 3 + 0);
            int v1 = __ldg(faces + f * 3 + 1);
            int v2 = __ldg(faces + f * 3 + 2);
            v0 = max(0, min(v0, NUM_VERTS - 1));
            v1 = max(0, min(v1, NUM_VERTS - 1));
            v2 = max(0, min(v2, NUM_VERTS - 1));
            const float w0 = bc[i * 3 + 0];
            const float w1 = bc[i * 3 + 1];
            const float w2 = bc[i * 3 + 2];
            const float* a0 = verts + v0 * 3;   // batch-0 slice only
            const float* a1 = verts + v1 * 3;
            const float* a2 = verts + v2 * 3;
            ox = w0 * __ldg(a0 + 0) + w1 * __ldg(a1 + 0) + w2 * __ldg(a2 + 0);
            oy = w0 * __ldg(a0 + 1) + w1 * __ldg(a1 + 1) + w2 * __ldg(a2 + 1);
            oz = w0 * __ldg(a0 + 2) + w1 * __ldg(a1 + 2) + w2 * __ldg(a2 + 2);
        }
        r[i * 3 + 0] = ox;
        r[i * 3 + 1] = oy;
        r[i * 3 + 2] = oz;
    }

    const float4 o0 = make_float4(r[0], r[1], r[2], r[3]);
    const float4 o1 = make_float4(r[4], r[5], r[6], r[7]);
    const float4 o2 = make_float4(r[8], r[9], r[10], r[11]);

    const size_t base = (size_t)p0 * 3;
#pragma unroll
    for (int n = 0; n < NB; n++) {
        float4* dst = reinterpret_cast<float4*>(out + (size_t)n * HW * 3 + base);
        dst[0] = o0;
        dst[1] = o1;
        dst[2] = o2;
    }
}

extern "C" void kernel_launch(void* const* d_in, const int* in_sizes, int n_in,
                              void* d_out, int out_size)
{
    const float* verts = (const float*)d_in[0];  // (16, 6890, 3) f32
    const int*   faces = (const int*)d_in[1];    // (13776, 3) i32
    const int*   pix   = (const int*)d_in[2];    // (1024, 1024) i32
    const float* bary  = (const float*)d_in[3];  // (1024, 1024, 3) f32
    float*       out   = (float*)d_out;          // (16, 1024, 1024, 3) f32

    const int threads = 256;
    const int total_thr = HW / 4;                // 262144
    const int blocks = (total_thr + threads - 1) / threads;
    uvrender_kernel<<<blocks, threads>>>(verts, faces, pix, bary, out);
}

// round 7
// speedup vs baseline: 1.3341x; 1.3341x over previous
#include <cuda_runtime.h>
#include <cstdint>

// Problem constants (fixed by the reference)
#define NUM_VERTS 6890
#define NUM_FACES 13776
#define HH 1024
#define WW 1024
#define NB 16
#define HW (HH * WW)

// ---------------------------------------------------------------------------
// Kernel A: compute the per-pixel interpolated attributes ONCE, write slice 0.
// Each thread handles 4 consecutive pixels -> 3 aligned float4 stores.
// faces/pix are int32 (harness canonicalizes int64 inputs to int32).
// ---------------------------------------------------------------------------
__global__ __launch_bounds__(256) void uvrender_compute(
    const float* __restrict__ verts,   // (16, 6890, 3) fp32; only batch 0 used
    const int*   __restrict__ faces,   // (13776, 3) int32
    const int*   __restrict__ pix,     // (1024, 1024) int32
    const float* __restrict__ bary,    // (1024, 1024, 3) fp32
    float* __restrict__ out)           // (16, 1024, 1024, 3) fp32 -> slice 0
{
    const int t = blockIdx.x * blockDim.x + threadIdx.x;
    const int p0 = t * 4;
    if (p0 >= HW) return;

    const int4 pv = *reinterpret_cast<const int4*>(pix + p0);
    int pf[4] = {pv.x, pv.y, pv.z, pv.w};

    const float4 b0 = *reinterpret_cast<const float4*>(bary + (size_t)p0 * 3);
    const float4 b1 = *reinterpret_cast<const float4*>(bary + (size_t)p0 * 3 + 4);
    const float4 b2 = *reinterpret_cast<const float4*>(bary + (size_t)p0 * 3 + 8);
    float bc[12] = {b0.x, b0.y, b0.z, b0.w,
                    b1.x, b1.y, b1.z, b1.w,
                    b2.x, b2.y, b2.z, b2.w};

    float r[12];
#pragma unroll
    for (int i = 0; i < 4; i++) {
        float ox = 0.f, oy = 0.f, oz = 0.f;
        int f = pf[i];
        if (f >= 0) {
            f = min(f, NUM_FACES - 1);               // defensive, dead in practice
            int v0 = __ldg(faces + f * 3 + 0);
            int v1 = __ldg(faces + f * 3 + 1);
            int v2 = __ldg(faces + f * 3 + 2);
            v0 = max(0, min(v0, NUM_VERTS - 1));
            v1 = max(0, min(v1, NUM_VERTS - 1));
            v2 = max(0, min(v2, NUM_VERTS - 1));
            const float w0 = bc[i * 3 + 0];
            const float w1 = bc[i * 3 + 1];
            const float w2 = bc[i * 3 + 2];
            const float* a0 = verts + v0 * 3;        // batch-0 slice only
            const float* a1 = verts + v1 * 3;
            const float* a2 = verts + v2 * 3;
            ox = w0 * __ldg(a0 + 0) + w1 * __ldg(a1 + 0) + w2 * __ldg(a2 + 0);
            oy = w0 * __ldg(a0 + 1) + w1 * __ldg(a1 + 1) + w2 * __ldg(a2 + 1);
            oz = w0 * __ldg(a0 + 2) + w1 * __ldg(a1 + 2) + w2 * __ldg(a2 + 2);
        }
        r[i * 3 + 0] = ox;
        r[i * 3 + 1] = oy;
        r[i * 3 + 2] = oz;
    }

    float4* dst = reinterpret_cast<float4*>(out + (size_t)p0 * 3);
    dst[0] = make_float4(r[0], r[1], r[2], r[3]);
    dst[1] = make_float4(r[4], r[5], r[6], r[7]);
    dst[2] = make_float4(r[8], r[9], r[10], r[11]);
}

// ---------------------------------------------------------------------------
// Kernel B: broadcast slice 0 -> slices 1..15. Pure streaming copy.
// Slice 0 (12 MiB) is L2-resident after kernel A; writes are 180 MiB of
// coalesced STG.128. One float4 per thread, 15 stores.
// ---------------------------------------------------------------------------
#define NV4 (HW * 3 / 4)   // 786432 float4 elements per slice

__global__ __launch_bounds__(256) void uvrender_broadcast(
    float* __restrict__ out)
{
    const int idx = blockIdx.x * blockDim.x + threadIdx.x;
    if (idx >= NV4) return;

    const float4 v = __ldg(reinterpret_cast<const float4*>(out) + idx);

#pragma unroll
    for (int n = 1; n < NB; n++) {
        reinterpret_cast<float4*>(out + (size_t)n * HW * 3)[idx] = v;
    }
}

extern "C" void kernel_launch(void* const* d_in, const int* in_sizes, int n_in,
                              void* d_out, int out_size)
{
    const float* verts = (const float*)d_in[0];  // (16, 6890, 3) f32
    const int*   faces = (const int*)d_in[1];    // (13776, 3) i32
    const int*   pix   = (const int*)d_in[2];    // (1024, 1024) i32
    const float* bary  = (const float*)d_in[3];  // (1024, 1024, 3) f32
    float*       out   = (float*)d_out;          // (16, 1024, 1024, 3) f32

    const int threads = 256;

    const int thrA = HW / 4;                     // 262144
    uvrender_compute<<<(thrA + threads - 1) / threads, threads>>>(
        verts, faces, pix, bary, out);

    uvrender_broadcast<<<(NV4 + threads - 1) / threads, threads>>>(out);
}

// round 9
// speedup vs baseline: 1.5834x; 1.1869x over previous
#include <cuda_runtime.h>
#include <cstdint>

// Problem constants (fixed by the reference)
#define NUM_VERTS 6890
#define NUM_FACES 13776
#define HH 1024
#define WW 1024
#define NB 16
#define HW (HH * WW)
#define NV4 (HW * 3 / 4)   // 786432 float4 elements per slice

// Pre-packed per-face vertex attributes: 3 float4 (xyz + pad) per face.
// 13776 * 3 * 16 B = 661 KB -> L2-resident. __device__ global = allowed scratch.
__device__ float4 g_fattr[NUM_FACES * 3];

// ---------------------------------------------------------------------------
// Kernel P: pack verts[0] attributes into face-major float4 table.
// One thread per face: 3 index loads + 9 scalar gathers + 3 float4 stores.
// ---------------------------------------------------------------------------
__global__ __launch_bounds__(256) void uvrender_prepack(
    const float* __restrict__ verts,   // (16, 6890, 3) fp32; batch 0 only
    const int*   __restrict__ faces)   // (13776, 3) int32
{
    const int f = blockIdx.x * blockDim.x + threadIdx.x;
    if (f >= NUM_FACES) return;

    int v0 = __ldg(faces + f * 3 + 0);
    int v1 = __ldg(faces + f * 3 + 1);
    int v2 = __ldg(faces + f * 3 + 2);
    v0 = max(0, min(v0, NUM_VERTS - 1));
    v1 = max(0, min(v1, NUM_VERTS - 1));
    v2 = max(0, min(v2, NUM_VERTS - 1));

    const float* a0 = verts + v0 * 3;
    const float* a1 = verts + v1 * 3;
    const float* a2 = verts + v2 * 3;
    g_fattr[f * 3 + 0] = make_float4(a0[0], a0[1], a0[2], 0.f);
    g_fattr[f * 3 + 1] = make_float4(a1[0], a1[1], a1[2], 0.f);
    g_fattr[f * 3 + 2] = make_float4(a2[0], a2[1], a2[2], 0.f);
}

// ---------------------------------------------------------------------------
// Kernel A: compute interpolated attributes ONCE, write slice 0.
// Per pixel: 3 float4 gathers from the packed table (vs 12 scalar gathers).
// Each thread handles 4 consecutive pixels -> 3 aligned float4 stores.
// ---------------------------------------------------------------------------
__global__ __launch_bounds__(256) void uvrender_compute(
    const int*   __restrict__ pix,     // (1024, 1024) int32
    const float* __restrict__ bary,    // (1024, 1024, 3) fp32
    float* __restrict__ out)           // slice 0 of (16, 1024, 1024, 3) fp32
{
    const int t = blockIdx.x * blockDim.x + threadIdx.x;
    const int p0 = t * 4;
    if (p0 >= HW) return;

    const int4 pv = *reinterpret_cast<const int4*>(pix + p0);
    int pf[4] = {pv.x, pv.y, pv.z, pv.w};

    const float4 b0 = *reinterpret_cast<const float4*>(bary + (size_t)p0 * 3);
    const float4 b1 = *reinterpret_cast<const float4*>(bary + (size_t)p0 * 3 + 4);
    const float4 b2 = *reinterpret_cast<const float4*>(bary + (size_t)p0 * 3 + 8);
    float bc[12] = {b0.x, b0.y, b0.z, b0.w,
                    b1.x, b1.y, b1.z, b1.w,
                    b2.x, b2.y, b2.z, b2.w};

    float r[12];
#pragma unroll
    for (int i = 0; i < 4; i++) {
        float ox = 0.f, oy = 0.f, oz = 0.f;
        int f = pf[i];
        if (f >= 0) {
            f = min(f, NUM_FACES - 1);              // defensive, dead in practice
            const float4 fa0 = __ldg(&g_fattr[f * 3 + 0]);
            const float4 fa1 = __ldg(&g_fattr[f * 3 + 1]);
            const float4 fa2 = __ldg(&g_fattr[f * 3 + 2]);
            const float w0 = bc[i * 3 + 0];
            const float w1 = bc[i * 3 + 1];
            const float w2 = bc[i * 3 + 2];
            ox = w0 * fa0.x + w1 * fa1.x + w2 * fa2.x;
            oy = w0 * fa0.y + w1 * fa1.y + w2 * fa2.y;
            oz = w0 * fa0.z + w1 * fa1.z + w2 * fa2.z;
        }
        r[i * 3 + 0] = ox;
        r[i * 3 + 1] = oy;
        r[i * 3 + 2] = oz;
    }

    float4* dst = reinterpret_cast<float4*>(out + (size_t)p0 * 3);
    dst[0] = make_float4(r[0], r[1], r[2], r[3]);
    dst[1] = make_float4(r[4], r[5], r[6], r[7]);
    dst[2] = make_float4(r[8], r[9], r[10], r[11]);
}

// ---------------------------------------------------------------------------
// Kernel B: broadcast slice 0 -> slices 1..15. Pure streaming copy.
// __stcs on stores keeps the 180 MiB write stream from evicting the
// L2-resident slice-0 source.
// ---------------------------------------------------------------------------
__global__ __launch_bounds__(256) void uvrender_broadcast(
    float* __restrict__ out)
{
    const int idx = blockIdx.x * blockDim.x + threadIdx.x;
    if (idx >= NV4) return;

    const float4 v = __ldg(reinterpret_cast<const float4*>(out) + idx);

#pragma unroll
    for (int n = 1; n < NB; n++) {
        __stcs(reinterpret_cast<float4*>(out + (size_t)n * HW * 3) + idx, v);
    }
}

extern "C" void kernel_launch(void* const* d_in, const int* in_sizes, int n_in,
                              void* d_out, int out_size)
{
    const float* verts = (const float*)d_in[0];  // (16, 6890, 3) f32
    const int*   faces = (const int*)d_in[1];    // (13776, 3) i32
    const int*   pix   = (const int*)d_in[2];    // (1024, 1024) i32
    const float* bary  = (const float*)d_in[3];  // (1024, 1024, 3) f32
    float*       out   = (float*)d_out;          // (16, 1024, 1024, 3) f32

    const int threads = 256;

    uvrender_prepack<<<(NUM_FACES + threads - 1) / threads, threads>>>(verts, faces);

    const int thrA = HW / 4;                     // 262144
    uvrender_compute<<<(thrA + threads - 1) / threads, threads>>>(pix, bary, out);

    uvrender_broadcast<<<(NV4 + threads - 1) / threads, threads>>>(out);
}